// round 12
// baseline (speedup 1.0000x reference)
#include <cuda_runtime.h>
#include <cuda_pipeline.h>
#include <cuda_bf16.h>
#include <math.h>

// Problem constants
#define B_   8
#define S_   1024
#define D_   1024
#define H_   16
#define KD_  64
#define VD_  64
#define NQK  2048          // H*KD*2
#define NV   1024          // H*VD
#define MROWS (B_*S_)      // 8192

// ---------------------------------------------------------------------------
// Scratch (static device arrays — no runtime allocation)
// ---------------------------------------------------------------------------
__device__ float g_qk [B_*S_*NQK];          // x @ W_qk^T + b   (f32)
__device__ float g_v  [B_*S_*NV];           // x @ W_v^T  + b   (f32)
__device__ __nv_bfloat16 g_qh[B_*H_*S_*KD_]; // Q bf16 [bh,s,kd], pre-scaled
__device__ __nv_bfloat16 g_kh[B_*H_*S_*KD_]; // K bf16 frag-major 8KB tiles
__device__ __nv_bfloat16 g_vh[B_*H_*S_*VD_]; // V bf16 frag-major 8KB tiles
__device__ __nv_bfloat16 g_aoh[B_*S_*NV];   // attention out (bf16)
__device__ __nv_bfloat16 g_xh [B_*S_*D_];   // bf16 x
__device__ __nv_bfloat16 g_wqkh[NQK*D_];    // bf16 W_qk
__device__ __nv_bfloat16 g_wvh [NV*D_];     // bf16 W_v
__device__ __nv_bfloat16 g_woh [D_*NV];     // bf16 W_o
__device__ float g_psum[512];
__device__ float g_psq [512];
__device__ float g_stats[16];               // per-batch {sum, sumsq}

// ---------------------------------------------------------------------------
// MMA helpers
// ---------------------------------------------------------------------------
// bf16 m16n8k16: a0=A[g][2t,2t+1], a1=A[g+8][2t,2t+1], a2=A[g][2t+8,2t+9],
// a3=A[g+8][2t+8,2t+9]; b0={B[2t][g],B[2t+1][g]}, b1={B[2t+8][g],B[2t+9][g]}.
__device__ __forceinline__ void mma_bf16(float& c0, float& c1, float& c2, float& c3,
                                         unsigned a0, unsigned a1, unsigned a2, unsigned a3,
                                         unsigned b0, unsigned b1) {
    asm volatile(
        "mma.sync.aligned.m16n8k16.row.col.f32.bf16.bf16.f32 "
        "{%0,%1,%2,%3}, {%4,%5,%6,%7}, {%8,%9}, {%0,%1,%2,%3};"
        : "+f"(c0), "+f"(c1), "+f"(c2), "+f"(c3)
        : "r"(a0), "r"(a1), "r"(a2), "r"(a3), "r"(b0), "r"(b1));
}

// FMA-pipe exp2 (no MUFU): deg-6 poly + exponent-field add
__device__ __forceinline__ float fexp2(float y) {
    y = fmaxf(y, -80.f);
    float tt = y + 12582912.f;                 // 1.5*2^23: round-to-nearest
    float f  = y - (tt - 12582912.f);          // f in [-0.5, 0.5]
    float p  = 1.5403530393381610e-4f;
    p = p * f + 1.3333558146428443e-3f;
    p = p * f + 9.6181291076284770e-3f;
    p = p * f + 5.5504108664821580e-2f;
    p = p * f + 2.4022650695910071e-1f;
    p = p * f + 6.9314718055994531e-1f;
    p = p * f + 1.0f;
    return __int_as_float(__float_as_int(p) + (__float_as_int(tt) << 23));
}

__device__ __forceinline__ unsigned packbf(float a, float b) {
    __nv_bfloat162 p = __floats2bfloat162_rn(a, b);
    return *reinterpret_cast<unsigned*>(&p);
}

// ---------------------------------------------------------------------------
// bf16 packing pass (rn rounding; cp.async then copies raw bf16)
// ---------------------------------------------------------------------------
__global__ void pack_bf16_kernel(__nv_bfloat16* __restrict__ dst,
                                 const float* __restrict__ src)
{
    int i = blockIdx.x * 256 + threadIdx.x;
    float4 v = reinterpret_cast<const float4*>(src)[i];
    uint2 o;
    o.x = packbf(v.x, v.y);
    o.y = packbf(v.z, v.w);
    reinterpret_cast<uint2*>(dst)[i] = o;
}

// ---------------------------------------------------------------------------
// bf16 tensor-core GEMM, cp.async 2-stage pipeline (unchanged from R9).
// ---------------------------------------------------------------------------
#define HP 20   // smem pitch in 32-bit words

__global__ __launch_bounds__(256, 2)
void hgemm_bias(const __nv_bfloat16* __restrict__ A, const __nv_bfloat16* __restrict__ W,
                const float* __restrict__ bias, float* __restrict__ C, int N)
{
    __shared__ unsigned As[2][128 * HP];
    __shared__ unsigned Ws[2][128 * HP];
    const int K = 1024;
    int tid = threadIdx.x;
    int warpId = tid >> 5, lane = tid & 31;
    int wm = warpId >> 2, wn = warpId & 3;
    int g = lane >> 2, t = lane & 3;
    int m0 = blockIdx.y * 128, n0 = blockIdx.x * 128;

    float c[4][4][4];
#pragma unroll
    for (int i = 0; i < 4; i++)
#pragma unroll
        for (int j = 0; j < 4; j++)
#pragma unroll
            for (int f = 0; f < 4; f++) c[i][j][f] = 0.f;

    auto load_stage = [&](int st, int k0) {
#pragma unroll
        for (int l = 0; l < 2; l++) {
            int idx = tid + l * 256;            // 0..511
            int r   = idx >> 2;                 // 0..127
            int cw  = (idx & 3) * 4;            // word offset 0,4,8,12
            __pipeline_memcpy_async(&As[st][r * HP + cw],
                                    &A[(size_t)(m0 + r) * K + k0 + cw * 2], 16);
            __pipeline_memcpy_async(&Ws[st][r * HP + cw],
                                    &W[(size_t)(n0 + r) * K + k0 + cw * 2], 16);
        }
    };

    load_stage(0, 0);
    __pipeline_commit();

    int cur = 0;
    for (int k0 = 0; k0 < K; k0 += 32) {
        if (k0 + 32 < K) {
            load_stage(cur ^ 1, k0 + 32);
            __pipeline_commit();
            __pipeline_wait_prior(1);
        } else {
            __pipeline_wait_prior(0);
        }
        __syncthreads();

#pragma unroll
        for (int ks = 0; ks < 2; ks++) {
            unsigned af[4][4], bf[4][2];
#pragma unroll
            for (int tm = 0; tm < 4; tm++) {
                int row = wm * 64 + tm * 16 + g;
                af[tm][0] = As[cur][row * HP + ks * 8 + t];
                af[tm][1] = As[cur][(row + 8) * HP + ks * 8 + t];
                af[tm][2] = As[cur][row * HP + ks * 8 + 4 + t];
                af[tm][3] = As[cur][(row + 8) * HP + ks * 8 + 4 + t];
            }
#pragma unroll
            for (int tn = 0; tn < 4; tn++) {
                int rowb = wn * 32 + tn * 8 + g;
                bf[tn][0] = Ws[cur][rowb * HP + ks * 8 + t];
                bf[tn][1] = Ws[cur][rowb * HP + ks * 8 + 4 + t];
            }
#pragma unroll
            for (int tm = 0; tm < 4; tm++)
#pragma unroll
                for (int tn = 0; tn < 4; tn++)
                    mma_bf16(c[tm][tn][0], c[tm][tn][1], c[tm][tn][2], c[tm][tn][3],
                             af[tm][0], af[tm][1], af[tm][2], af[tm][3],
                             bf[tn][0], bf[tn][1]);
        }
        __syncthreads();
        cur ^= 1;
    }

#pragma unroll
    for (int tm = 0; tm < 4; tm++) {
        int row = m0 + wm * 64 + tm * 16 + g;
#pragma unroll
        for (int tn = 0; tn < 4; tn++) {
            int col = n0 + wn * 32 + tn * 8 + 2 * t;
            float2 o0, o1;
            o0.x = c[tm][tn][0] + bias[col];
            o0.y = c[tm][tn][1] + bias[col + 1];
            o1.x = c[tm][tn][2] + bias[col];
            o1.y = c[tm][tn][3] + bias[col + 1];
            *reinterpret_cast<float2*>(&C[(size_t)row * N + col])       = o0;
            *reinterpret_cast<float2*>(&C[(size_t)(row + 8) * N + col]) = o1;
        }
    }
}

// ---------------------------------------------------------------------------
// O-projection (bf16 MMA): C = A @ W_o^T + b_o + x, + LN partials
// ---------------------------------------------------------------------------
__global__ __launch_bounds__(256, 2)
void hgemm_oproj(const __nv_bfloat16* __restrict__ A, const __nv_bfloat16* __restrict__ W,
                 const float* __restrict__ bias, const float* __restrict__ x,
                 float* __restrict__ C)
{
    __shared__ unsigned As[2][128 * HP];
    __shared__ unsigned Ws[2][128 * HP];
    const int K = 1024, N = 1024;
    int tid = threadIdx.x;
    int warpId = tid >> 5, lane = tid & 31;
    int wm = warpId >> 2, wn = warpId & 3;
    int g = lane >> 2, t = lane & 3;
    int m0 = blockIdx.y * 128, n0 = blockIdx.x * 128;

    float c[4][4][4];
#pragma unroll
    for (int i = 0; i < 4; i++)
#pragma unroll
        for (int j = 0; j < 4; j++)
#pragma unroll
            for (int f = 0; f < 4; f++) c[i][j][f] = 0.f;

    auto load_stage = [&](int st, int k0) {
#pragma unroll
        for (int l = 0; l < 2; l++) {
            int idx = tid + l * 256;
            int r   = idx >> 2;
            int cw  = (idx & 3) * 4;
            __pipeline_memcpy_async(&As[st][r * HP + cw],
                                    &A[(size_t)(m0 + r) * K + k0 + cw * 2], 16);
            __pipeline_memcpy_async(&Ws[st][r * HP + cw],
                                    &W[(size_t)(n0 + r) * K + k0 + cw * 2], 16);
        }
    };

    load_stage(0, 0);
    __pipeline_commit();

    int cur = 0;
    for (int k0 = 0; k0 < K; k0 += 32) {
        if (k0 + 32 < K) {
            load_stage(cur ^ 1, k0 + 32);
            __pipeline_commit();
            __pipeline_wait_prior(1);
        } else {
            __pipeline_wait_prior(0);
        }
        __syncthreads();

#pragma unroll
        for (int ks = 0; ks < 2; ks++) {
            unsigned af[4][4], bf[4][2];
#pragma unroll
            for (int tm = 0; tm < 4; tm++) {
                int row = wm * 64 + tm * 16 + g;
                af[tm][0] = As[cur][row * HP + ks * 8 + t];
                af[tm][1] = As[cur][(row + 8) * HP + ks * 8 + t];
                af[tm][2] = As[cur][row * HP + ks * 8 + 4 + t];
                af[tm][3] = As[cur][(row + 8) * HP + ks * 8 + 4 + t];
            }
#pragma unroll
            for (int tn = 0; tn < 4; tn++) {
                int rowb = wn * 32 + tn * 8 + g;
                bf[tn][0] = Ws[cur][rowb * HP + ks * 8 + t];
                bf[tn][1] = Ws[cur][rowb * HP + ks * 8 + 4 + t];
            }
#pragma unroll
            for (int tm = 0; tm < 4; tm++)
#pragma unroll
                for (int tn = 0; tn < 4; tn++)
                    mma_bf16(c[tm][tn][0], c[tm][tn][1], c[tm][tn][2], c[tm][tn][3],
                             af[tm][0], af[tm][1], af[tm][2], af[tm][3],
                             bf[tn][0], bf[tn][1]);
        }
        __syncthreads();
        cur ^= 1;
    }

    float lsum = 0.f, lsq = 0.f;
#pragma unroll
    for (int tm = 0; tm < 4; tm++) {
        int row = m0 + wm * 64 + tm * 16 + g;
#pragma unroll
        for (int tn = 0; tn < 4; tn++) {
            int col = n0 + wn * 32 + tn * 8 + 2 * t;
            float2 x0 = *reinterpret_cast<const float2*>(&x[(size_t)row * N + col]);
            float2 x1 = *reinterpret_cast<const float2*>(&x[(size_t)(row + 8) * N + col]);
            float2 o0, o1;
            o0.x = c[tm][tn][0] + bias[col]     + x0.x;
            o0.y = c[tm][tn][1] + bias[col + 1] + x0.y;
            o1.x = c[tm][tn][2] + bias[col]     + x1.x;
            o1.y = c[tm][tn][3] + bias[col + 1] + x1.y;
            *reinterpret_cast<float2*>(&C[(size_t)row * N + col])       = o0;
            *reinterpret_cast<float2*>(&C[(size_t)(row + 8) * N + col]) = o1;
            lsum += o0.x + o0.y + o1.x + o1.y;
            lsq  += o0.x*o0.x + o0.y*o0.y + o1.x*o1.x + o1.y*o1.y;
        }
    }
#pragma unroll
    for (int off = 16; off > 0; off >>= 1) {
        lsum += __shfl_down_sync(0xffffffffu, lsum, off);
        lsq  += __shfl_down_sync(0xffffffffu, lsq,  off);
    }
    __shared__ float rs[8], rq[8];
    if (lane == 0) { rs[warpId] = lsum; rq[warpId] = lsq; }
    __syncthreads();
    if (tid == 0) {
        float s = 0.f, q = 0.f;
#pragma unroll
        for (int w = 0; w < 8; w++) { s += rs[w]; q += rq[w]; }
        int p = blockIdx.y * 8 + blockIdx.x;   // 0..511, 64 per batch
        g_psum[p] = s; g_psq[p] = q;
    }
}

// ---------------------------------------------------------------------------
// Repack: de-interleave qk/v into bf16.
//   Q -> [bh,s,kd] bf16, pre-scaled by QSCL (kd pairs packed per word)
//   K -> frag-major 8KB tiles: word ((k*4+n2)*32 + g*4+t)*4 + npar*2+bh,
//        packing K[j][16k+8bh+2t .. +1]; n-side from j: n2=jl>>4,npar,g=jl&7
//   V -> frag-major 8KB tiles: word packs {V[j][vd], V[j+1][vd]} with
//        j=16k+8jh+2t; n-side from vd.
// Block handles TWO s-rows so V's (j,j+1) pairs pack into single words.
// ---------------------------------------------------------------------------
#define QSCL_ (0.125f * 1.4426950408889634f)   // 1/sqrt(64) * log2(e)

__global__ void repack_kernel()
{
    __shared__ float sqk[2][2048 + 64];
    __shared__ float sv [2][1024 + 32];
    int sp = blockIdx.x;              // 0..4095
    int b  = sp >> 9;
    int s0 = (sp & 511) * 2;
    int tid = threadIdx.x;            // 256
    const float* qk0 = g_qk + ((size_t)(b * S_) + s0) * NQK;
    const float* v0  = g_v  + ((size_t)(b * S_) + s0) * NV;
#pragma unroll
    for (int r = 0; r < 2; r++) {
        for (int c = tid; c < 2048; c += 256) sqk[r][c + (c >> 5)] = qk0[(size_t)r * NQK + c];
        for (int c = tid; c < 1024; c += 256) sv [r][c + (c >> 5)] = v0 [(size_t)r * NV  + c];
    }
    __syncthreads();

    int jt  = s0 >> 6;
    int jl0 = s0 & 63;
    unsigned* qh = reinterpret_cast<unsigned*>(g_qh);
    unsigned* kh = reinterpret_cast<unsigned*>(g_kh);
    unsigned* vh = reinterpret_cast<unsigned*>(g_vh);

    // Q + K: (r, h, kd2) -> 2*16*32 = 1024 words each
    for (int idx = tid; idx < 1024; idx += 256) {
        int r = idx >> 9, rem = idx & 511;
        int h = rem >> 5, kd2 = rem & 31;
        int s = s0 + r, jl = jl0 + r;
        size_t bh = (size_t)(b * H_ + h);
        int cq0 = (2 * kd2) * 32 + h, cq1 = cq0 + 32;
        float q0 = sqk[r][cq0 + (cq0 >> 5)];
        float q1 = sqk[r][cq1 + (cq1 >> 5)];
        qh[(bh * S_ + s) * 32 + kd2] = packbf(q0 * QSCL_, q1 * QSCL_);
        int ck0 = cq0 + 16, ck1 = cq1 + 16;
        float k0 = sqk[r][ck0 + (ck0 >> 5)];
        float k1 = sqk[r][ck1 + (ck1 >> 5)];
        int kk = kd2 >> 3, bhf = (kd2 >> 2) & 1, t = kd2 & 3;
        int n2 = jl >> 4, npar = (jl >> 3) & 1, g = jl & 7;
        kh[(bh * 16 + jt) * 2048 +
           (size_t)(((kk * 4 + n2) * 32 + g * 4 + t) * 4 + npar * 2 + bhf)] =
            packbf(k0, k1);
    }

    // V: (h, vd) -> 1024 words, each packs rows (s0, s0+1)
    {
        int kk = jl0 >> 4, jh = (jl0 >> 3) & 1, t = (jl0 & 7) >> 1;
        for (int idx = tid; idx < 1024; idx += 256) {
            int h = idx >> 6, vd = idx & 63;
            int cv = vd * 16 + h;
            float va = sv[0][cv + (cv >> 5)];
            float vb = sv[1][cv + (cv >> 5)];
            int n2 = vd >> 4, npar = (vd >> 3) & 1, g = vd & 7;
            vh[((size_t)(b * H_ + h) * 16 + jt) * 2048 +
               (size_t)(((kk * 4 + n2) * 32 + g * 4 + t) * 4 + npar * 2 + jh)] =
                packbf(va, vb);
        }
    }
}

// ---------------------------------------------------------------------------
// bf16 tensor-core flash attention; register-resident P (S c-frag == P a-frag
// for m16n8k16); K/V frag-major 8KB tiles via cp.async 2-stage pipeline.
// CTA = (b, h, 128 q-rows); 8 warps, warp owns 16 rows; j-tiles of 64.
// ---------------------------------------------------------------------------
#define TILE_HW 2048                    // words per bf16 frag tile
#define AT_SMEM_BYTES (4 * TILE_HW * 4) // 2xK + 2xV = 32KB

__global__ __launch_bounds__(256, 2)
void attn_tc_kernel()
{
    extern __shared__ unsigned smu[];
    unsigned* Ks = smu;                  // [2][2048]
    unsigned* Vs = smu + 2 * TILE_HW;    // [2][2048]

    int tid  = threadIdx.x;
    int warp = tid >> 5, lane = tid & 31;
    int g = lane >> 2, t = lane & 3;
    int i0 = blockIdx.x * 128;
    int h  = blockIdx.y, b = blockIdx.z;
    int bh = b * H_ + h;
    const unsigned* Qw = reinterpret_cast<const unsigned*>(g_qh) +
                         ((size_t)bh * S_ + i0) * 32;
    const unsigned* Kb = reinterpret_cast<const unsigned*>(g_kh) + (size_t)bh * 16 * TILE_HW;
    const unsigned* Vb = reinterpret_cast<const unsigned*>(g_vh) + (size_t)bh * 16 * TILE_HW;

    auto load_kv = [&](int st, int jt) {
        const unsigned* Kt = Kb + (size_t)jt * TILE_HW;
        const unsigned* Vt = Vb + (size_t)jt * TILE_HW;
#pragma unroll
        for (int l = 0; l < 2; l++) {
            int idx = tid + l * 256;        // 0..511
            __pipeline_memcpy_async(&Ks[st * TILE_HW + idx * 4], &Kt[idx * 4], 16);
            __pipeline_memcpy_async(&Vs[st * TILE_HW + idx * 4], &Vt[idx * 4], 16);
        }
    };

    load_kv(0, 0);
    __pipeline_commit();

    // Q a-frags straight from gmem (bf16 words, pre-scaled)
    int wr = warp * 16;
    unsigned qf[4][4];
#pragma unroll
    for (int k = 0; k < 4; k++) {
        qf[k][0] = Qw[(wr + g)     * 32 + k * 8 + t];
        qf[k][1] = Qw[(wr + g + 8) * 32 + k * 8 + t];
        qf[k][2] = Qw[(wr + g)     * 32 + k * 8 + 4 + t];
        qf[k][3] = Qw[(wr + g + 8) * 32 + k * 8 + 4 + t];
    }

    float accO[8][4];
#pragma unroll
    for (int n = 0; n < 8; n++)
#pragma unroll
        for (int f = 0; f < 4; f++) accO[n][f] = 0.f;
    float m0 = -1e30f, m1 = -1e30f, l0 = 0.f, l1 = 0.f;

    int cur = 0;
    for (int jt = 0; jt < 16; jt++) {
        if (jt + 1 < 16) {
            load_kv(cur ^ 1, jt + 1);
            __pipeline_commit();
            __pipeline_wait_prior(1);
        } else {
            __pipeline_wait_prior(0);
        }
        __syncthreads();
        const uint4* K4 = reinterpret_cast<const uint4*>(Ks + cur * TILE_HW);
        const uint4* V4 = reinterpret_cast<const uint4*>(Vs + cur * TILE_HW);

        // S = Q K^T  (warp: 16 x 64), 4 k16-steps, one LDS.128 per (k,n2)
        float sacc[8][4];
#pragma unroll
        for (int n = 0; n < 8; n++)
#pragma unroll
            for (int f = 0; f < 4; f++) sacc[n][f] = 0.f;
#pragma unroll
        for (int k = 0; k < 4; k++) {
#pragma unroll
            for (int n2 = 0; n2 < 4; n2++) {
                uint4 bb = K4[(k * 4 + n2) * 32 + lane];
                mma_bf16(sacc[2*n2][0], sacc[2*n2][1], sacc[2*n2][2], sacc[2*n2][3],
                         qf[k][0], qf[k][1], qf[k][2], qf[k][3], bb.x, bb.y);
                mma_bf16(sacc[2*n2+1][0], sacc[2*n2+1][1], sacc[2*n2+1][2], sacc[2*n2+1][3],
                         qf[k][0], qf[k][1], qf[k][2], qf[k][3], bb.z, bb.w);
            }
        }

        // online softmax (rows wr+g, wr+g+8), exp2 on FMA pipe
        float tm0 = -1e30f, tm1 = -1e30f;
#pragma unroll
        for (int n = 0; n < 8; n++) {
            tm0 = fmaxf(tm0, fmaxf(sacc[n][0], sacc[n][1]));
            tm1 = fmaxf(tm1, fmaxf(sacc[n][2], sacc[n][3]));
        }
        tm0 = fmaxf(tm0, __shfl_xor_sync(0xffffffffu, tm0, 1));
        tm0 = fmaxf(tm0, __shfl_xor_sync(0xffffffffu, tm0, 2));
        tm1 = fmaxf(tm1, __shfl_xor_sync(0xffffffffu, tm1, 1));
        tm1 = fmaxf(tm1, __shfl_xor_sync(0xffffffffu, tm1, 2));
        float mn0 = fmaxf(m0, tm0), mn1 = fmaxf(m1, tm1);
        float sc0 = fexp2(m0 - mn0), sc1 = fexp2(m1 - mn1);
        float ps0 = 0.f, ps1 = 0.f;
        unsigned pp0[8], pp1[8];       // P a-frag words, register-resident
#pragma unroll
        for (int n = 0; n < 8; n++) {
            float p0 = fexp2(sacc[n][0] - mn0);
            float p1 = fexp2(sacc[n][1] - mn0);
            float p2 = fexp2(sacc[n][2] - mn1);
            float p3 = fexp2(sacc[n][3] - mn1);
            ps0 += p0 + p1; ps1 += p2 + p3;
            pp0[n] = packbf(p0, p1);   // row g
            pp1[n] = packbf(p2, p3);   // row g+8
            accO[n][0] *= sc0; accO[n][1] *= sc0;
            accO[n][2] *= sc1; accO[n][3] *= sc1;
        }
        ps0 += __shfl_xor_sync(0xffffffffu, ps0, 1);
        ps0 += __shfl_xor_sync(0xffffffffu, ps0, 2);
        ps1 += __shfl_xor_sync(0xffffffffu, ps1, 1);
        ps1 += __shfl_xor_sync(0xffffffffu, ps1, 2);
        l0 = l0 * sc0 + ps0;
        l1 = l1 * sc1 + ps1;
        m0 = mn0; m1 = mn1;

        // O += P V : A = {pp0[2k], pp1[2k], pp0[2k+1], pp1[2k+1]} per k-step
#pragma unroll
        for (int k = 0; k < 4; k++) {
#pragma unroll
            for (int n2 = 0; n2 < 4; n2++) {
                uint4 bb = V4[(k * 4 + n2) * 32 + lane];
                mma_bf16(accO[2*n2][0], accO[2*n2][1], accO[2*n2][2], accO[2*n2][3],
                         pp0[2*k], pp1[2*k], pp0[2*k+1], pp1[2*k+1], bb.x, bb.y);
                mma_bf16(accO[2*n2+1][0], accO[2*n2+1][1], accO[2*n2+1][2], accO[2*n2+1][3],
                         pp0[2*k], pp1[2*k], pp0[2*k+1], pp1[2*k+1], bb.z, bb.w);
            }
        }
        __syncthreads();  // stage cur may be overwritten next iteration
        cur ^= 1;
    }

    // epilogue: normalize, write bf16 (oproj raw-copies it)
    float inv0 = 1.f / l0, inv1 = 1.f / l1;
    int row0 = i0 + wr + g, row1 = row0 + 8;
#pragma unroll
    for (int n = 0; n < 8; n++) {
        int col = h * 64 + n * 8 + 2 * t;
        unsigned o0 = packbf(accO[n][0] * inv0, accO[n][1] * inv0);
        unsigned o1 = packbf(accO[n][2] * inv1, accO[n][3] * inv1);
        *reinterpret_cast<unsigned*>(&g_aoh[(size_t)(b * S_ + row0) * NV + col]) = o0;
        *reinterpret_cast<unsigned*>(&g_aoh[(size_t)(b * S_ + row1) * NV + col]) = o1;
    }
}

// ---------------------------------------------------------------------------
// LN stats reduce + finalize
// ---------------------------------------------------------------------------
__global__ void stats_reduce()
{
    int w = threadIdx.x >> 5, lane = threadIdx.x & 31;
    float s = g_psum[w * 64 + lane] + g_psum[w * 64 + 32 + lane];
    float q = g_psq [w * 64 + lane] + g_psq [w * 64 + 32 + lane];
#pragma unroll
    for (int off = 16; off > 0; off >>= 1) {
        s += __shfl_down_sync(0xffffffffu, s, off);
        q += __shfl_down_sync(0xffffffffu, q, off);
    }
    if (lane == 0) { g_stats[2 * w] = s; g_stats[2 * w + 1] = q; }
}

__global__ void ln_finalize(float* __restrict__ y,
                            const float* __restrict__ lnw,
                            const float* __restrict__ lnb)
{
    int idx = blockIdx.x * 256 + threadIdx.x;
    int b   = idx >> 18;
    int sd4 = idx & ((1 << 18) - 1);
    const float invn = 1.0f / 1048576.0f;
    float mean = g_stats[2 * b] * invn;
    float var  = g_stats[2 * b + 1] * invn - mean * mean;
    float inv  = rsqrtf(var + 1e-5f);
    float4 v  = reinterpret_cast<float4*>(y)[idx];
    float4 w  = reinterpret_cast<const float4*>(lnw)[sd4];
    float4 bb = reinterpret_cast<const float4*>(lnb)[sd4];
    v.x = (v.x - mean) * inv * w.x + bb.x;
    v.y = (v.y - mean) * inv * w.y + bb.y;
    v.z = (v.z - mean) * inv * w.z + bb.z;
    v.w = (v.w - mean) * inv * w.w + bb.w;
    reinterpret_cast<float4*>(y)[idx] = v;
}

// ---------------------------------------------------------------------------
// kernel_launch
// ---------------------------------------------------------------------------
extern "C" void kernel_launch(void* const* d_in, const int* in_sizes, int n_in,
                              void* d_out, int out_size)
{
    const float* x    = (const float*)d_in[0];
    const float* W_qk = (const float*)d_in[1];
    const float* b_qk = (const float*)d_in[2];
    const float* W_v  = (const float*)d_in[3];
    const float* b_v  = (const float*)d_in[4];
    const float* W_o  = (const float*)d_in[5];
    const float* b_o  = (const float*)d_in[6];
    const float* ln_w = (const float*)d_in[7];
    const float* ln_b = (const float*)d_in[8];
    float* out = (float*)d_out;

    void *p_qk, *p_v, *p_aoh, *p_xh, *p_wqkh, *p_wvh, *p_woh;
    cudaGetSymbolAddress(&p_qk,   g_qk);
    cudaGetSymbolAddress(&p_v,    g_v);
    cudaGetSymbolAddress(&p_aoh,  g_aoh);
    cudaGetSymbolAddress(&p_xh,   g_xh);
    cudaGetSymbolAddress(&p_wqkh, g_wqkh);
    cudaGetSymbolAddress(&p_wvh,  g_wvh);
    cudaGetSymbolAddress(&p_woh,  g_woh);

    cudaFuncSetAttribute(attn_tc_kernel, cudaFuncAttributeMaxDynamicSharedMemorySize,
                         AT_SMEM_BYTES);

    // 0) bf16 packing of x + weights
    pack_bf16_kernel<<<(B_*S_*D_) / 1024, 256>>>((__nv_bfloat16*)p_xh,   x);
    pack_bf16_kernel<<<(NQK*D_)   / 1024, 256>>>((__nv_bfloat16*)p_wqkh, W_qk);
    pack_bf16_kernel<<<(NV*D_)    / 1024, 256>>>((__nv_bfloat16*)p_wvh,  W_v);
    pack_bf16_kernel<<<(D_*NV)    / 1024, 256>>>((__nv_bfloat16*)p_woh,  W_o);

    // 1) qk = x @ W_qk^T + b_qk   (8192 x 2048) — bf16 MMA
    hgemm_bias<<<dim3(NQK / 128, MROWS / 128), 256>>>((const __nv_bfloat16*)p_xh,
                                                      (const __nv_bfloat16*)p_wqkh, b_qk,
                                                      (float*)p_qk, NQK);
    // 2) v  = x @ W_v^T + b_v     (8192 x 1024) — bf16 MMA
    hgemm_bias<<<dim3(NV / 128, MROWS / 128), 256>>>((const __nv_bfloat16*)p_xh,
                                                     (const __nv_bfloat16*)p_wvh, b_v,
                                                     (float*)p_v, NV);
    // 3) repack: Q bf16 row-major (pre-scaled); K/V bf16 frag-major tiles
    repack_kernel<<<MROWS / 2, 256>>>();
    // 4) flash attention — bf16 MMA, register-resident P, cp.async pipeline
    attn_tc_kernel<<<dim3(S_ / 128, H_, B_), 256, AT_SMEM_BYTES>>>();
    // 5) O-proj (bf16 MMA) + bias + residual + partial LN stats
    hgemm_oproj<<<dim3(NV / 128, MROWS / 128), 256>>>((const __nv_bfloat16*)p_aoh,
                                                      (const __nv_bfloat16*)p_woh, b_o, x, out);
    // 6) reduce stats per batch
    stats_reduce<<<1, 256>>>();
    // 7) LayerNorm finalize
    ln_finalize<<<(B_ * S_ * D_ / 4) / 256, 256>>>(out, ln_w, ln_b);
}